// round 4
// baseline (speedup 1.0000x reference)
#include <cuda_runtime.h>
#include <cstdint>

// Problem shape (fixed by the reference)
#define NN 8192
#define DD 64
#define HH 256

#define THREADS 256          // 8 warps; 64 rows/block, 4-way H-split per row
#define ROWS_PER_BLOCK 64

// smem: W1 [64][256] | W2 [256][64] | z[256]=t*wt+b1 | s[256] | b2[64]
#define SMEM_FLOATS (DD*HH + HH*DD + HH + HH + DD)
#define SMEM_BYTES  (SMEM_FLOATS * sizeof(float))

__global__ __launch_bounds__(THREADS, 1)
void ode_kernel(const float* __restrict__ tptr, const float* __restrict__ y,
                const float* __restrict__ W1, const float* __restrict__ b1,
                const float* __restrict__ wt, const float* __restrict__ W2,
                const float* __restrict__ b2, float* __restrict__ out)
{
    extern __shared__ float smem[];
    float* sW1 = smem;                 // [64][256], row-major (as in gmem)
    float* sW2 = smem + DD * HH;       // [256][64], row-major
    float* sz  = sW2 + HH * DD;        // [256]
    float* ss  = sz + HH;              // [256]
    float* sb2 = ss + HH;              // [64]

    const int tid = threadIdx.x;

    // ---- cooperative weight staging (coalesced float4 copies) ----
    {
        const float4* w1v = (const float4*)W1;
        float4* sw1v = (float4*)sW1;
        #pragma unroll
        for (int i = 0; i < (DD*HH)/4/THREADS; i++)
            sw1v[tid + i*THREADS] = w1v[tid + i*THREADS];
        const float4* w2v = (const float4*)W2;
        float4* sw2v = (float4*)sW2;
        #pragma unroll
        for (int i = 0; i < (HH*DD)/4/THREADS; i++)
            sw2v[tid + i*THREADS] = w2v[tid + i*THREADS];
    }
    // ---- per-hidden-unit constants: z_j = t*wt_j + b1_j ; s_j = sum_d W1[d,j]*W2[j,d] ----
    {
        const float tv = tptr[0];
        sz[tid] = tv * wt[tid] + b1[tid];
        float s = 0.f;
        #pragma unroll
        for (int d = 0; d < DD; d++)
            s += W1[d*HH + tid] * W2[tid*DD + d];
        ss[tid] = s;
        if (tid < DD) sb2[tid] = b2[tid];
    }
    __syncthreads();

    // ---- thread mapping: warp w handles 8 rows; lane bits[0:3)=row-in-warp, bits[3:5)=j-group ----
    const int lane = tid & 31;
    const int warp = tid >> 5;
    const int g    = lane >> 3;                       // j-subset 0..3 (64 hidden units each)
    const int r    = (warp << 3) | (lane & 7);        // row within block, 0..63
    const int row  = blockIdx.x * ROWS_PER_BLOCK + r;

    // load this row of y into registers (16 x LDG.128)
    float yreg[DD];
    {
        const float4* yv = (const float4*)(y + (size_t)row * DD);
        #pragma unroll
        for (int i = 0; i < DD/4; i++) {
            float4 v = yv[i];
            yreg[4*i+0] = v.x; yreg[4*i+1] = v.y;
            yreg[4*i+2] = v.z; yreg[4*i+3] = v.w;
        }
    }

    float dy[DD];
    #pragma unroll
    for (int d = 0; d < DD; d++) dy[d] = 0.f;
    float divacc = 0.f;

    const int jb0 = g * 64;

    // 16 chunks of 4 hidden units each
    #pragma unroll 1
    for (int jj = 0; jj < 16; jj++) {
        const int jbase = jb0 + jj * 4;

        // pre-activation for 4 hidden units: a = z + y @ W1[:, jbase:jbase+4]
        float4 a = *(const float4*)(sz + jbase);
        const float* w1p = sW1 + jbase;
        #pragma unroll
        for (int k = 0; k < DD; k++) {
            float4 w = *(const float4*)(w1p + k*HH);   // broadcast LDS.128
            a.x += yreg[k] * w.x;
            a.y += yreg[k] * w.y;
            a.z += yreg[k] * w.z;
            a.w += yreg[k] * w.w;
        }
        const float h0 = tanhf(a.x);
        const float h1 = tanhf(a.y);
        const float h2 = tanhf(a.z);
        const float h3 = tanhf(a.w);

        // divergence contribution: (1 - h^2) * s_j
        {
            float4 sv = *(const float4*)(ss + jbase);
            divacc += (1.f - h0*h0) * sv.x;
            divacc += (1.f - h1*h1) * sv.y;
            divacc += (1.f - h2*h2) * sv.z;
            divacc += (1.f - h3*h3) * sv.w;
        }

        // dy += h_j * W2[j, :] for the 4 units
        const float* w20 = sW2 + (jbase + 0) * DD;
        const float* w21 = sW2 + (jbase + 1) * DD;
        const float* w22 = sW2 + (jbase + 2) * DD;
        const float* w23 = sW2 + (jbase + 3) * DD;
        #pragma unroll
        for (int d = 0; d < DD; d += 4) {
            float4 wa = *(const float4*)(w20 + d);
            float4 wb = *(const float4*)(w21 + d);
            float4 wc = *(const float4*)(w22 + d);
            float4 wd = *(const float4*)(w23 + d);
            dy[d+0] += h0*wa.x + h1*wb.x + h2*wc.x + h3*wd.x;
            dy[d+1] += h0*wa.y + h1*wb.y + h2*wc.y + h3*wd.y;
            dy[d+2] += h0*wa.z + h1*wb.z + h2*wc.z + h3*wd.z;
            dy[d+3] += h0*wa.w + h1*wb.w + h2*wc.w + h3*wd.w;
        }
    }

    // ---- allreduce across the 4 j-groups (lane bits 3,4) ----
    const unsigned m = 0xffffffffu;
    #pragma unroll
    for (int d = 0; d < DD; d++) {
        float v = dy[d];
        v += __shfl_xor_sync(m, v, 8);
        v += __shfl_xor_sync(m, v, 16);
        dy[d] = v;
    }
    divacc += __shfl_xor_sync(m, divacc, 8);
    divacc += __shfl_xor_sync(m, divacc, 16);

    // ---- store: lane with group g writes cols [16g, 16g+16); g==0 writes -div at col 64 ----
    float* orow = out + (size_t)row * (DD + 1);
    #pragma unroll
    for (int c = 0; c < DD; c++) {
        if ((c >> 4) == g)                 // compile-time c, runtime g -> predicated STG
            orow[c] = dy[c] + sb2[c];
    }
    if (g == 0) orow[DD] = -divacc;
}

extern "C" void kernel_launch(void* const* d_in, const int* in_sizes, int n_in,
                              void* d_out, int out_size) {
    const float* t  = (const float*)d_in[0];
    const float* y  = (const float*)d_in[1];
    const float* W1 = (const float*)d_in[2];
    const float* b1 = (const float*)d_in[3];
    const float* wt = (const float*)d_in[4];
    const float* W2 = (const float*)d_in[5];
    const float* b2 = (const float*)d_in[6];
    float* out = (float*)d_out;

    const int n = in_sizes[1] / DD;            // 8192
    const int blocks = n / ROWS_PER_BLOCK;     // 128

    cudaFuncSetAttribute(ode_kernel,
                         cudaFuncAttributeMaxDynamicSharedMemorySize, SMEM_BYTES);
    ode_kernel<<<blocks, THREADS, SMEM_BYTES>>>(t, y, W1, b1, wt, W2, b2, out);
}

// round 5
// speedup vs baseline: 1.4396x; 1.4396x over previous
#include <cuda_runtime.h>
#include <cstdint>

// Shape fixed by the reference
#define DD 64
#define HH 256
#define ROWS 64            // rows per block
#define THREADS 256        // 8 warps
#define HPAD 260           // h row stride (words): 16B-aligned, 4*HPAD%32=16 -> de-conflicted

// smem layout (floats)
#define OFF_W1 0
#define OFF_W2 (OFF_W1 + DD*HH)           // 16384
#define OFF_Y  (OFF_W2 + HH*DD)           // +16384
#define OFF_H  (OFF_Y + ROWS*DD)          // +4096
#define OFF_Z  (OFF_H + ROWS*HPAD)        // +16640
#define OFF_S  (OFF_Z + HH)
#define OFF_B2 (OFF_S + HH)
#define SMEM_FLOATS (OFF_B2 + DD)
#define SMEM_BYTES  (SMEM_FLOATS * sizeof(float))   // ~212 KB

__device__ __forceinline__ float tanh_ap(float x) {
    float r;
    asm("tanh.approx.f32 %0, %1;" : "=f"(r) : "f"(x));
    return r;
}

__global__ __launch_bounds__(THREADS, 1)
void ode_kernel(const float* __restrict__ tptr, const float* __restrict__ y,
                const float* __restrict__ W1, const float* __restrict__ b1,
                const float* __restrict__ wt, const float* __restrict__ W2,
                const float* __restrict__ b2, float* __restrict__ out)
{
    extern __shared__ float sm[];
    float* sW1 = sm + OFF_W1;   // [64][256]
    float* sW2 = sm + OFF_W2;   // [256][64]
    float* sy  = sm + OFF_Y;    // [64][64]
    float* sh  = sm + OFF_H;    // [64][HPAD]
    float* sz  = sm + OFF_Z;    // [256]
    float* ss  = sm + OFF_S;    // [256]
    float* sb2 = sm + OFF_B2;   // [64]

    const int tid = threadIdx.x;

    // ---- stage weights + y tile (coalesced float4) ----
    {
        const float4* src = (const float4*)W1;
        float4* dst = (float4*)sW1;
        #pragma unroll
        for (int i = 0; i < (DD*HH)/4/THREADS; i++)
            dst[tid + i*THREADS] = src[tid + i*THREADS];
        src = (const float4*)W2; dst = (float4*)sW2;
        #pragma unroll
        for (int i = 0; i < (HH*DD)/4/THREADS; i++)
            dst[tid + i*THREADS] = src[tid + i*THREADS];
        const float4* ys = (const float4*)(y + (size_t)blockIdx.x * ROWS * DD);
        float4* yd = (float4*)sy;
        #pragma unroll
        for (int i = 0; i < (ROWS*DD)/4/THREADS; i++)
            yd[tid + i*THREADS] = ys[tid + i*THREADS];
    }
    // ---- per-hidden-unit constants ----
    {
        const float tv = tptr[0];
        sz[tid] = tv * wt[tid] + b1[tid];
        float s = 0.f;
        #pragma unroll
        for (int d = 0; d < DD; d++)
            s += W1[d*HH + tid] * W2[tid*DD + d];
        ss[tid] = s;
        if (tid < DD) sb2[tid] = b2[tid];
    }
    __syncthreads();

    // =========== Phase 1: H = tanh(Y @ W1 + z), 8x8 tile / thread ===========
    {
        const int rt = tid >> 5;          // warp id -> row tile (8 rows)
        const int ct = tid & 31;          // col tile (8 cols)
        const int r0 = rt * 8, c0 = ct * 8;

        float acc[8][8];
        {
            float4 z0 = *(const float4*)(sz + c0);
            float4 z1 = *(const float4*)(sz + c0 + 4);
            #pragma unroll
            for (int r = 0; r < 8; r++) {
                acc[r][0] = z0.x; acc[r][1] = z0.y; acc[r][2] = z0.z; acc[r][3] = z0.w;
                acc[r][4] = z1.x; acc[r][5] = z1.y; acc[r][6] = z1.z; acc[r][7] = z1.w;
            }
        }

        #pragma unroll 1
        for (int k0 = 0; k0 < DD; k0 += 4) {
            float ya[8][4];
            #pragma unroll
            for (int r = 0; r < 8; r++) {
                float4 v = *(const float4*)(sy + (r0 + r)*DD + k0);   // warp broadcast
                ya[r][0] = v.x; ya[r][1] = v.y; ya[r][2] = v.z; ya[r][3] = v.w;
            }
            float4 w0[4], w1[4];
            #pragma unroll
            for (int kk = 0; kk < 4; kk++) {
                w0[kk] = *(const float4*)(sW1 + (k0 + kk)*HH + c0);
                w1[kk] = *(const float4*)(sW1 + (k0 + kk)*HH + c0 + 4);
            }
            #pragma unroll
            for (int r = 0; r < 8; r++) {
                #pragma unroll
                for (int kk = 0; kk < 4; kk++) {
                    const float yk = ya[r][kk];
                    acc[r][0] += yk * w0[kk].x;
                    acc[r][1] += yk * w0[kk].y;
                    acc[r][2] += yk * w0[kk].z;
                    acc[r][3] += yk * w0[kk].w;
                    acc[r][4] += yk * w1[kk].x;
                    acc[r][5] += yk * w1[kk].y;
                    acc[r][6] += yk * w1[kk].z;
                    acc[r][7] += yk * w1[kk].w;
                }
            }
        }

        #pragma unroll
        for (int r = 0; r < 8; r++) {
            float4 o0, o1;
            o0.x = tanh_ap(acc[r][0]); o0.y = tanh_ap(acc[r][1]);
            o0.z = tanh_ap(acc[r][2]); o0.w = tanh_ap(acc[r][3]);
            o1.x = tanh_ap(acc[r][4]); o1.y = tanh_ap(acc[r][5]);
            o1.z = tanh_ap(acc[r][6]); o1.w = tanh_ap(acc[r][7]);
            *(float4*)(sh + (r0 + r)*HPAD + c0)     = o0;
            *(float4*)(sh + (r0 + r)*HPAD + c0 + 4) = o1;
        }
    }
    __syncthreads();

    // =========== Divergence: div_r = sum_j (1 - h_rj^2) * s_j ===========
    {
        const int r = tid >> 2;           // 0..63
        const int q = tid & 3;            // quarter of hidden dim
        const float* hp = sh + r*HPAD + q*64;
        const float* sp = ss + q*64;
        float dv = 0.f;
        #pragma unroll
        for (int j = 0; j < 64; j += 4) {
            float4 hv = *(const float4*)(hp + j);
            float4 sv = *(const float4*)(sp + j);
            dv += (1.f - hv.x*hv.x) * sv.x;
            dv += (1.f - hv.y*hv.y) * sv.y;
            dv += (1.f - hv.z*hv.z) * sv.z;
            dv += (1.f - hv.w*hv.w) * sv.w;
        }
        dv += __shfl_xor_sync(0xffffffffu, dv, 1);
        dv += __shfl_xor_sync(0xffffffffu, dv, 2);
        if (q == 0)
            out[(size_t)(blockIdx.x*ROWS + r)*(DD+1) + DD] = -dv;
    }

    // =========== Phase 2: DY = H @ W2 + b2, 4x4 tile / thread ===========
    {
        const int rt = tid >> 4;          // 0..15
        const int ct = tid & 15;          // 0..15
        const int r0 = rt * 4, c0 = ct * 4;

        float acc[4][4];
        #pragma unroll
        for (int r = 0; r < 4; r++)
            #pragma unroll
            for (int c = 0; c < 4; c++) acc[r][c] = 0.f;

        #pragma unroll 2
        for (int k0 = 0; k0 < HH; k0 += 4) {
            float ha[4][4];
            #pragma unroll
            for (int r = 0; r < 4; r++) {
                float4 v = *(const float4*)(sh + (r0 + r)*HPAD + k0);
                ha[r][0] = v.x; ha[r][1] = v.y; ha[r][2] = v.z; ha[r][3] = v.w;
            }
            float4 ww[4];
            #pragma unroll
            for (int kk = 0; kk < 4; kk++)
                ww[kk] = *(const float4*)(sW2 + (k0 + kk)*DD + c0);
            #pragma unroll
            for (int r = 0; r < 4; r++) {
                #pragma unroll
                for (int kk = 0; kk < 4; kk++) {
                    const float hk = ha[r][kk];
                    acc[r][0] += hk * ww[kk].x;
                    acc[r][1] += hk * ww[kk].y;
                    acc[r][2] += hk * ww[kk].z;
                    acc[r][3] += hk * ww[kk].w;
                }
            }
        }

        const float4 bb = *(const float4*)(sb2 + c0);
        #pragma unroll
        for (int r = 0; r < 4; r++) {
            float* op = out + (size_t)(blockIdx.x*ROWS + r0 + r)*(DD+1) + c0;
            op[0] = acc[r][0] + bb.x;
            op[1] = acc[r][1] + bb.y;
            op[2] = acc[r][2] + bb.z;
            op[3] = acc[r][3] + bb.w;
        }
    }
}

extern "C" void kernel_launch(void* const* d_in, const int* in_sizes, int n_in,
                              void* d_out, int out_size) {
    const float* t  = (const float*)d_in[0];
    const float* y  = (const float*)d_in[1];
    const float* W1 = (const float*)d_in[2];
    const float* b1 = (const float*)d_in[3];
    const float* wt = (const float*)d_in[4];
    const float* W2 = (const float*)d_in[5];
    const float* b2 = (const float*)d_in[6];
    float* out = (float*)d_out;

    const int n = in_sizes[1] / DD;          // 8192
    const int blocks = n / ROWS;             // 128

    cudaFuncSetAttribute(ode_kernel,
                         cudaFuncAttributeMaxDynamicSharedMemorySize, SMEM_BYTES);
    ode_kernel<<<blocks, THREADS, SMEM_BYTES>>>(t, y, W1, b1, wt, W2, b2, out);
}